// round 3
// baseline (speedup 1.0000x reference)
#include <cuda_runtime.h>

// Problem constants (fixed instance: B=2048, T=2048, H=51)
#define H_  51
#define HP  52          // padded hidden
#define JP  208         // 4*HP padded gate count
#define RR  16          // batch rows per CTA
#define NT  832         // threads per CTA (26 warps)
#define TT  2048
#define BB  2048
#define PSTRIDE 20      // smem partial stride (conflict-free for 128-bit ops)

// Repacked weights (device globals; prep kernel fills them each launch)
__device__ float g_W1p[HP*JP];   // [k][j] layer-1 W_hh, padded
__device__ float g_W2a[HP*JP];   // [k][j] layer-2 W_ih
__device__ float g_W2b[HP*JP];   // [k][j] layer-2 W_hh
__device__ float g_b1[JP];
__device__ float g_wx[JP];
__device__ float g_b2[JP];
__device__ float g_wlin[HP];
__device__ float g_blin[1];

__global__ void prep_kernel(const float* __restrict__ W_ih1, const float* __restrict__ W_hh1,
                            const float* __restrict__ b_ih1, const float* __restrict__ b_hh1,
                            const float* __restrict__ W_ih2, const float* __restrict__ W_hh2,
                            const float* __restrict__ b_ih2, const float* __restrict__ b_hh2,
                            const float* __restrict__ W_lin, const float* __restrict__ b_lin)
{
    int stride = gridDim.x * blockDim.x;
    int i0 = blockIdx.x * blockDim.x + threadIdx.x;
    for (int idx = i0; idx < HP*JP; idx += stride) {
        int k = idx / JP, j = idx % JP;
        int g = j / HP, n = j % HP;
        bool v = (n < H_) && (k < H_);
        int ro = g*H_ + n;
        g_W1p[idx] = v ? W_hh1[ro*H_ + k] : 0.f;
        g_W2a[idx] = v ? W_ih2[ro*H_ + k] : 0.f;
        g_W2b[idx] = v ? W_hh2[ro*H_ + k] : 0.f;
    }
    for (int j = i0; j < JP; j += stride) {
        int g = j / HP, n = j % HP;
        bool v = (n < H_);
        int ro = g*H_ + n;
        g_b1[j] = v ? (b_ih1[ro] + b_hh1[ro]) : 0.f;
        g_wx[j] = v ? W_ih1[ro] : 0.f;
        g_b2[j] = v ? (b_ih2[ro] + b_hh2[ro]) : 0.f;
    }
    for (int n = i0; n < HP; n += stride) g_wlin[n] = (n < H_) ? W_lin[n] : 0.f;
    if (i0 == 0) g_blin[0] = b_lin[0];
}

// HW tanh (sm_75+): 1 MUFU op instead of ex2+rcp chains
__device__ __forceinline__ float tanha(float x) {
    float r; asm("tanh.approx.f32 %0, %1;" : "=f"(r) : "f"(x)); return r;
}
__device__ __forceinline__ float siga(float x) {
    return fmaf(0.5f, tanha(0.5f*x), 0.5f);
}

// ---- packed f32x2 helpers (PTX-only; ptxas won't auto-fuse) ----
__device__ __forceinline__ unsigned long long pk2(float w) {
    unsigned long long r;
    asm("mov.b64 %0, {%1, %1};" : "=l"(r) : "f"(w));
    return r;
}
__device__ __forceinline__ void fma2(unsigned long long& a, unsigned long long w, unsigned long long h) {
    asm("fma.rn.f32x2 %0, %1, %2, %3;" : "=l"(a) : "l"(w), "l"(h), "l"(a));
}

__global__ __launch_bounds__(NT, 1)
void lstm_kernel(const float* __restrict__ input, float* __restrict__ out)
{
    extern __shared__ float sm[];
    float* p1  = sm;                   // NT*PSTRIDE = 16640 floats
    float* p2  = p1 + NT*PSTRIDE;      // 16640
    float* h1s = p2 + NT*PSTRIDE;      // HP*RR = 832   layout [k][r]
    float* h2s = h1s + HP*RR;          // 832
    float* xs  = h2s + HP*RR;          // RR
    float* wls = xs + RR;              // HP
    float* b2s = wls + HP;             // JP

    const int tid  = threadIdx.x;
    const int row0 = blockIdx.x * RR;

    // phase-1 task: gate row j1, k-quarter kq (13 k's)
    const int j1 = tid >> 2, kq = tid & 3;
    // phase-2 task: src (0 = W_ih2·h1, 1 = W_hh2·h2), gate row j2, k-half kh (26 k's)
    const int src = (tid >= 416) ? 1 : 0;
    const int jj  = tid - src*416;
    const int j2  = jj >> 1, kh = jj & 1;
    // update task: single (cell n, row ur)
    const int un = tid >> 4, ur = tid & 15;

    // register-resident weights: 13 + 26 = 39 regs
    float w1[13];
#pragma unroll
    for (int kk = 0; kk < 13; kk++)
        w1[kk] = g_W1p[(kq*13 + kk)*JP + j1];
    float w2[26];
    {
        const float* Ws = src ? g_W2b : g_W2a;
#pragma unroll
        for (int kk = 0; kk < 26; kk++) w2[kk] = Ws[(kh*26 + kk)*JP + j2];
    }
    const float bias1 = g_b1[j1];
    const float wx    = g_wx[j1];
    const float blin  = g_blin[0];

    // cell state: one cell per thread per layer
    float c1 = 0.f, c2 = 0.f;

    for (int i = tid; i < HP*RR; i += NT) { h1s[i] = 0.f; h2s[i] = 0.f; }
    for (int i = tid; i < HP; i += NT) wls[i] = g_wlin[i];
    for (int i = tid; i < JP; i += NT) b2s[i] = g_b2[i];
    if (tid >= RR && tid < 2*RR) xs[tid - RR] = input[(row0 + tid - RR)*TT + 0];
    __syncthreads();

    for (int t = 0; t < TT; t++) {
        // prefetch next x early (long-latency LDG hidden behind the step)
        float xnext = 0.f;
        if (tid >= RR && tid < 2*RR && (t + 1) < TT)
            xnext = __ldg(&input[(row0 + tid - RR)*TT + t + 1]);

        // output for step t-1 (threads 0..15; h2s stable until update2)
        if (tid < RR && t > 0) {
            float s0 = 0.f, s1 = 0.f, s2 = 0.f, s3 = 0.f;
#pragma unroll
            for (int n = 0; n < HP; n += 4) {
                s0 = fmaf(wls[n+0], h2s[(n+0)*RR + tid], s0);
                s1 = fmaf(wls[n+1], h2s[(n+1)*RR + tid], s1);
                s2 = fmaf(wls[n+2], h2s[(n+2)*RR + tid], s2);
                s3 = fmaf(wls[n+3], h2s[(n+3)*RR + tid], s3);
            }
            out[(row0 + tid)*TT + (t - 1)] = (s0 + s1) + (s2 + s3) + blin;
        }

        // ---- phase 1: quarter-dots (13 k) of gates1 over 16 rows (f32x2) ----
        {
            unsigned long long acc[RR/2];
            if (kq == 0) {
                unsigned long long wxp = pk2(wx);
                unsigned long long b1p = pk2(bias1);
                const ulonglong2* xv = reinterpret_cast<const ulonglong2*>(xs);
#pragma unroll
                for (int rv = 0; rv < RR/4; rv++) {
                    ulonglong2 x2 = xv[rv];
                    acc[2*rv+0] = b1p; fma2(acc[2*rv+0], wxp, x2.x);
                    acc[2*rv+1] = b1p; fma2(acc[2*rv+1], wxp, x2.y);
                }
            } else {
#pragma unroll
                for (int r = 0; r < RR/2; r++) acc[r] = 0ULL;
            }
            const ulonglong2* hbase =
                reinterpret_cast<const ulonglong2*>(h1s + kq*13*RR);
#pragma unroll
            for (int kk = 0; kk < 13; kk++) {
                unsigned long long w = pk2(w1[kk]);
#pragma unroll
                for (int rv = 0; rv < RR/4; rv++) {
                    ulonglong2 h = hbase[kk*(RR/4) + rv];
                    fma2(acc[2*rv+0], w, h.x);
                    fma2(acc[2*rv+1], w, h.y);
                }
            }
            ulonglong2* pw = reinterpret_cast<ulonglong2*>(p1 + tid*PSTRIDE);
#pragma unroll
            for (int rv = 0; rv < RR/4; rv++) {
                ulonglong2 v; v.x = acc[2*rv+0]; v.y = acc[2*rv+1];
                pw[rv] = v;
            }
        }
        __syncthreads();

        // ---- update 1: LSTM cell for (un, ur); 4 k-quarter partials per gate ----
        {
            int n = un;
            float gi = (p1[((0*HP+n)*4+0)*PSTRIDE + ur] + p1[((0*HP+n)*4+1)*PSTRIDE + ur])
                     + (p1[((0*HP+n)*4+2)*PSTRIDE + ur] + p1[((0*HP+n)*4+3)*PSTRIDE + ur]);
            float gf = (p1[((1*HP+n)*4+0)*PSTRIDE + ur] + p1[((1*HP+n)*4+1)*PSTRIDE + ur])
                     + (p1[((1*HP+n)*4+2)*PSTRIDE + ur] + p1[((1*HP+n)*4+3)*PSTRIDE + ur]);
            float gg = (p1[((2*HP+n)*4+0)*PSTRIDE + ur] + p1[((2*HP+n)*4+1)*PSTRIDE + ur])
                     + (p1[((2*HP+n)*4+2)*PSTRIDE + ur] + p1[((2*HP+n)*4+3)*PSTRIDE + ur]);
            float go = (p1[((3*HP+n)*4+0)*PSTRIDE + ur] + p1[((3*HP+n)*4+1)*PSTRIDE + ur])
                     + (p1[((3*HP+n)*4+2)*PSTRIDE + ur] + p1[((3*HP+n)*4+3)*PSTRIDE + ur]);
            c1 = siga(gf)*c1 + siga(gi)*tanha(gg);
            h1s[n*RR + ur] = siga(go)*tanha(c1);
        }
        __syncthreads();

        // ---- phase 2: half-dots (26 k) of W_ih2·h1new or W_hh2·h2 (f32x2) ----
        {
            unsigned long long acc[RR/2];
#pragma unroll
            for (int r = 0; r < RR/2; r++) acc[r] = 0ULL;
            const ulonglong2* hbase =
                reinterpret_cast<const ulonglong2*>((src ? h2s : h1s) + kh*26*RR);
#pragma unroll
            for (int kk = 0; kk < 26; kk++) {
                unsigned long long w = pk2(w2[kk]);
#pragma unroll
                for (int rv = 0; rv < RR/4; rv++) {
                    ulonglong2 h = hbase[kk*(RR/4) + rv];
                    fma2(acc[2*rv+0], w, h.x);
                    fma2(acc[2*rv+1], w, h.y);
                }
            }
            ulonglong2* pw = reinterpret_cast<ulonglong2*>(p2 + tid*PSTRIDE);
#pragma unroll
            for (int rv = 0; rv < RR/4; rv++) {
                ulonglong2 v; v.x = acc[2*rv+0]; v.y = acc[2*rv+1];
                pw[rv] = v;
            }
        }
        __syncthreads();

        // ---- update 2: cell (un, ur); partials: 2 src × 2 kh, + bias ----
        {
            int n = un;
            float gi = (p2[((0*HP+n)*2+0)*PSTRIDE + ur] + p2[((0*HP+n)*2+1)*PSTRIDE + ur])
                     + (p2[(416 + (0*HP+n)*2+0)*PSTRIDE + ur] + p2[(416 + (0*HP+n)*2+1)*PSTRIDE + ur])
                     + b2s[0*HP+n];
            float gf = (p2[((1*HP+n)*2+0)*PSTRIDE + ur] + p2[((1*HP+n)*2+1)*PSTRIDE + ur])
                     + (p2[(416 + (1*HP+n)*2+0)*PSTRIDE + ur] + p2[(416 + (1*HP+n)*2+1)*PSTRIDE + ur])
                     + b2s[1*HP+n];
            float gg = (p2[((2*HP+n)*2+0)*PSTRIDE + ur] + p2[((2*HP+n)*2+1)*PSTRIDE + ur])
                     + (p2[(416 + (2*HP+n)*2+0)*PSTRIDE + ur] + p2[(416 + (2*HP+n)*2+1)*PSTRIDE + ur])
                     + b2s[2*HP+n];
            float go = (p2[((3*HP+n)*2+0)*PSTRIDE + ur] + p2[((3*HP+n)*2+1)*PSTRIDE + ur])
                     + (p2[(416 + (3*HP+n)*2+0)*PSTRIDE + ur] + p2[(416 + (3*HP+n)*2+1)*PSTRIDE + ur])
                     + b2s[3*HP+n];
            c2 = siga(gf)*c2 + siga(gi)*tanha(gg);
            h2s[n*RR + ur] = siga(go)*tanha(c2);
        }
        if (tid >= RR && tid < 2*RR && (t + 1) < TT) xs[tid - RR] = xnext;
        __syncthreads();
    }

    // final output column (t = TT-1)
    if (tid < RR) {
        float s0 = 0.f, s1 = 0.f, s2 = 0.f, s3 = 0.f;
#pragma unroll
        for (int n = 0; n < HP; n += 4) {
            s0 = fmaf(wls[n+0], h2s[(n+0)*RR + tid], s0);
            s1 = fmaf(wls[n+1], h2s[(n+1)*RR + tid], s1);
            s2 = fmaf(wls[n+2], h2s[(n+2)*RR + tid], s2);
            s3 = fmaf(wls[n+3], h2s[(n+3)*RR + tid], s3);
        }
        out[(row0 + tid)*TT + (TT - 1)] = (s0 + s1) + (s2 + s3) + blin;
    }
}

extern "C" void kernel_launch(void* const* d_in, const int* in_sizes, int n_in,
                              void* d_out, int out_size)
{
    const float* input = (const float*)d_in[0];
    const float* W_ih1 = (const float*)d_in[1];
    const float* W_hh1 = (const float*)d_in[2];
    const float* b_ih1 = (const float*)d_in[3];
    const float* b_hh1 = (const float*)d_in[4];
    const float* W_ih2 = (const float*)d_in[5];
    const float* W_hh2 = (const float*)d_in[6];
    const float* b_ih2 = (const float*)d_in[7];
    const float* b_hh2 = (const float*)d_in[8];
    const float* W_lin = (const float*)d_in[9];
    const float* b_lin = (const float*)d_in[10];
    float* out = (float*)d_out;

    const int smem_bytes = (NT*PSTRIDE*2 + HP*RR*2 + RR + HP + JP) * (int)sizeof(float);
    cudaFuncSetAttribute(lstm_kernel, cudaFuncAttributeMaxDynamicSharedMemorySize, smem_bytes);

    prep_kernel<<<64, 256>>>(W_ih1, W_hh1, b_ih1, b_hh1,
                             W_ih2, W_hh2, b_ih2, b_hh2, W_lin, b_lin);
    lstm_kernel<<<BB/RR, NT, smem_bytes>>>(input, out);
}

// round 5
// speedup vs baseline: 2.0234x; 2.0234x over previous
#include <cuda_runtime.h>

// Problem constants (fixed instance: B=2048, T=2048, H=51)
#define H_  51
#define HP  52          // padded hidden
#define JP  208         // 4*HP padded gate count
#define RR  16          // batch rows per CTA
#define NT  832         // threads per CTA (26 warps)
#define TT  2048
#define BB  2048
#define PSTRIDE 20      // smem partial stride

// Repacked weights (device globals; prep kernel fills them each launch)
__device__ float g_W1p[HP*JP];   // [k][j] layer-1 W_hh, padded
__device__ float g_W2a[HP*JP];   // [k][j] layer-2 W_ih
__device__ float g_W2b[HP*JP];   // [k][j] layer-2 W_hh
__device__ float g_b1[JP];
__device__ float g_wx[JP];
__device__ float g_b2[JP];
__device__ float g_wlin[HP];
__device__ float g_blin[1];

__global__ void prep_kernel(const float* __restrict__ W_ih1, const float* __restrict__ W_hh1,
                            const float* __restrict__ b_ih1, const float* __restrict__ b_hh1,
                            const float* __restrict__ W_ih2, const float* __restrict__ W_hh2,
                            const float* __restrict__ b_ih2, const float* __restrict__ b_hh2,
                            const float* __restrict__ W_lin, const float* __restrict__ b_lin)
{
    int stride = gridDim.x * blockDim.x;
    int i0 = blockIdx.x * blockDim.x + threadIdx.x;
    for (int idx = i0; idx < HP*JP; idx += stride) {
        int k = idx / JP, j = idx % JP;
        int g = j / HP, n = j % HP;
        bool v = (n < H_) && (k < H_);
        int ro = g*H_ + n;
        g_W1p[idx] = v ? W_hh1[ro*H_ + k] : 0.f;
        g_W2a[idx] = v ? W_ih2[ro*H_ + k] : 0.f;
        g_W2b[idx] = v ? W_hh2[ro*H_ + k] : 0.f;
    }
    for (int j = i0; j < JP; j += stride) {
        int g = j / HP, n = j % HP;
        bool v = (n < H_);
        int ro = g*H_ + n;
        g_b1[j] = v ? (b_ih1[ro] + b_hh1[ro]) : 0.f;
        g_wx[j] = v ? W_ih1[ro] : 0.f;
        g_b2[j] = v ? (b_ih2[ro] + b_hh2[ro]) : 0.f;
    }
    for (int n = i0; n < HP; n += stride) g_wlin[n] = (n < H_) ? W_lin[n] : 0.f;
    if (i0 == 0) g_blin[0] = b_lin[0];
}

// HW tanh (sm_75+): single MUFU op
__device__ __forceinline__ float tanha(float x) {
    float r; asm("tanh.approx.f32 %0, %1;" : "=f"(r) : "f"(x)); return r;
}
__device__ __forceinline__ float siga(float x) {
    return fmaf(0.5f, tanha(0.5f*x), 0.5f);
}

// ---- packed f32x2 helpers (PTX-only; ptxas won't auto-fuse) ----
__device__ __forceinline__ unsigned long long pk2(float w) {
    unsigned long long r;
    asm("mov.b64 %0, {%1, %1};" : "=l"(r) : "f"(w));
    return r;
}
__device__ __forceinline__ void fma2(unsigned long long& a, unsigned long long w, unsigned long long h) {
    asm("fma.rn.f32x2 %0, %1, %2, %3;" : "=l"(a) : "l"(w), "l"(h), "l"(a));
}

__global__ __launch_bounds__(NT, 1)
void lstm_kernel(const float* __restrict__ input, float* __restrict__ out)
{
    extern __shared__ float sm[];
    float* p1  = sm;                   // NT*PSTRIDE = 16640 floats
    float* p2  = p1 + NT*PSTRIDE;      // 16640
    float* h1s = p2 + NT*PSTRIDE;      // HP*RR = 832   layout [k][r]
    float* h2s = h1s + HP*RR;          // 832
    float* xs  = h2s + HP*RR;          // RR
    float* wls = xs + RR;              // HP
    float* b2s = wls + HP;             // JP

    const int tid  = threadIdx.x;
    const int row0 = blockIdx.x * RR;

    // phase-1 task: k-quarter in HIGH bits (warp-uniform), gate row in LOW bits
    const int kq = tid / JP;           // 0..3  (832 = 4*208)
    const int j1 = tid - kq*JP;        // 0..207
    // phase-2 task: src / k-half in HIGH bits, gate row in LOW bits
    const int src = tid / 416;                 // 0 = W_ih2·h1, 1 = W_hh2·h2
    const int jj  = tid - src*416;
    const int kh  = jj / JP;                   // 0..1
    const int j2  = jj - kh*JP;                // 0..207
    // update task: single (cell n, row ur)
    const int un = tid >> 4, ur = tid & 15;

    // register-resident weights: 13 + 26 = 39 regs
    float w1[13];
#pragma unroll
    for (int kk = 0; kk < 13; kk++)
        w1[kk] = g_W1p[(kq*13 + kk)*JP + j1];
    float w2[26];
    {
        const float* Ws = src ? g_W2b : g_W2a;
#pragma unroll
        for (int kk = 0; kk < 26; kk++) w2[kk] = Ws[(kh*26 + kk)*JP + j2];
    }
    const float bias1 = g_b1[j1];
    const float wx    = g_wx[j1];
    const float blin  = g_blin[0];

    // cell state: one cell per thread per layer
    float c1 = 0.f, c2 = 0.f;

    for (int i = tid; i < HP*RR; i += NT) { h1s[i] = 0.f; h2s[i] = 0.f; }
    for (int i = tid; i < HP; i += NT) wls[i] = g_wlin[i];
    for (int i = tid; i < JP; i += NT) b2s[i] = g_b2[i];
    if (tid >= RR && tid < 2*RR) xs[tid - RR] = input[(row0 + tid - RR)*TT + 0];
    __syncthreads();

    for (int t = 0; t < TT; t++) {
        // prefetch next x early (long-latency LDG hidden behind the step)
        float xnext = 0.f;
        if (tid >= RR && tid < 2*RR && (t + 1) < TT)
            xnext = __ldg(&input[(row0 + tid - RR)*TT + t + 1]);

        // output for step t-1 (threads 0..15; h2s stable until update2)
        if (tid < RR && t > 0) {
            float s0 = 0.f, s1 = 0.f, s2 = 0.f, s3 = 0.f;
#pragma unroll
            for (int n = 0; n < HP; n += 4) {
                s0 = fmaf(wls[n+0], h2s[(n+0)*RR + tid], s0);
                s1 = fmaf(wls[n+1], h2s[(n+1)*RR + tid], s1);
                s2 = fmaf(wls[n+2], h2s[(n+2)*RR + tid], s2);
                s3 = fmaf(wls[n+3], h2s[(n+3)*RR + tid], s3);
            }
            out[(row0 + tid)*TT + (t - 1)] = (s0 + s1) + (s2 + s3) + blin;
        }

        // ---- phase 1: quarter-dots (13 k) of gates1 over 16 rows (f32x2) ----
        {
            unsigned long long acc[RR/2];
            if (kq == 0) {
                unsigned long long wxp = pk2(wx);
                unsigned long long b1p = pk2(bias1);
                const ulonglong2* xv = reinterpret_cast<const ulonglong2*>(xs);
#pragma unroll
                for (int rv = 0; rv < RR/4; rv++) {
                    ulonglong2 x2 = xv[rv];
                    acc[2*rv+0] = b1p; fma2(acc[2*rv+0], wxp, x2.x);
                    acc[2*rv+1] = b1p; fma2(acc[2*rv+1], wxp, x2.y);
                }
            } else {
#pragma unroll
                for (int r = 0; r < RR/2; r++) acc[r] = 0ULL;
            }
            const ulonglong2* hbase =
                reinterpret_cast<const ulonglong2*>(h1s + kq*13*RR);
#pragma unroll
            for (int kk = 0; kk < 13; kk++) {
                unsigned long long w = pk2(w1[kk]);
#pragma unroll
                for (int rv = 0; rv < RR/4; rv++) {
                    ulonglong2 h = hbase[kk*(RR/4) + rv];
                    fma2(acc[2*rv+0], w, h.x);
                    fma2(acc[2*rv+1], w, h.y);
                }
            }
            ulonglong2* pw = reinterpret_cast<ulonglong2*>(p1 + tid*PSTRIDE);
#pragma unroll
            for (int rv = 0; rv < RR/4; rv++) {
                ulonglong2 v; v.x = acc[2*rv+0]; v.y = acc[2*rv+1];
                pw[rv] = v;
            }
        }
        __syncthreads();

        // ---- update 1: LSTM cell for (un, ur); partial q at p1[(q*JP + j)] ----
        {
            int n = un;
            float gi = (p1[(0*JP + 0*HP+n)*PSTRIDE + ur] + p1[(1*JP + 0*HP+n)*PSTRIDE + ur])
                     + (p1[(2*JP + 0*HP+n)*PSTRIDE + ur] + p1[(3*JP + 0*HP+n)*PSTRIDE + ur]);
            float gf = (p1[(0*JP + 1*HP+n)*PSTRIDE + ur] + p1[(1*JP + 1*HP+n)*PSTRIDE + ur])
                     + (p1[(2*JP + 1*HP+n)*PSTRIDE + ur] + p1[(3*JP + 1*HP+n)*PSTRIDE + ur]);
            float gg = (p1[(0*JP + 2*HP+n)*PSTRIDE + ur] + p1[(1*JP + 2*HP+n)*PSTRIDE + ur])
                     + (p1[(2*JP + 2*HP+n)*PSTRIDE + ur] + p1[(3*JP + 2*HP+n)*PSTRIDE + ur]);
            float go = (p1[(0*JP + 3*HP+n)*PSTRIDE + ur] + p1[(1*JP + 3*HP+n)*PSTRIDE + ur])
                     + (p1[(2*JP + 3*HP+n)*PSTRIDE + ur] + p1[(3*JP + 3*HP+n)*PSTRIDE + ur]);
            c1 = siga(gf)*c1 + siga(gi)*tanha(gg);
            h1s[n*RR + ur] = siga(go)*tanha(c1);
        }
        __syncthreads();

        // ---- phase 2: half-dots (26 k) of W_ih2·h1new or W_hh2·h2 (f32x2) ----
        {
            unsigned long long acc[RR/2];
#pragma unroll
            for (int r = 0; r < RR/2; r++) acc[r] = 0ULL;
            const ulonglong2* hbase =
                reinterpret_cast<const ulonglong2*>((src ? h2s : h1s) + kh*26*RR);
#pragma unroll
            for (int kk = 0; kk < 26; kk++) {
                unsigned long long w = pk2(w2[kk]);
#pragma unroll
                for (int rv = 0; rv < RR/4; rv++) {
                    ulonglong2 h = hbase[kk*(RR/4) + rv];
                    fma2(acc[2*rv+0], w, h.x);
                    fma2(acc[2*rv+1], w, h.y);
                }
            }
            ulonglong2* pw = reinterpret_cast<ulonglong2*>(p2 + tid*PSTRIDE);
#pragma unroll
            for (int rv = 0; rv < RR/4; rv++) {
                ulonglong2 v; v.x = acc[2*rv+0]; v.y = acc[2*rv+1];
                pw[rv] = v;
            }
        }
        __syncthreads();

        // ---- update 2: cell (un, ur); partial (src,kh) at p2[(src*416+kh*JP+j)] ----
        {
            int n = un;
            float gi = (p2[(0*416 + 0*JP + 0*HP+n)*PSTRIDE + ur] + p2[(0*416 + 1*JP + 0*HP+n)*PSTRIDE + ur])
                     + (p2[(1*416 + 0*JP + 0*HP+n)*PSTRIDE + ur] + p2[(1*416 + 1*JP + 0*HP+n)*PSTRIDE + ur])
                     + b2s[0*HP+n];
            float gf = (p2[(0*416 + 0*JP + 1*HP+n)*PSTRIDE + ur] + p2[(0*416 + 1*JP + 1*HP+n)*PSTRIDE + ur])
                     + (p2[(1*416 + 0*JP + 1*HP+n)*PSTRIDE + ur] + p2[(1*416 + 1*JP + 1*HP+n)*PSTRIDE + ur])
                     + b2s[1*HP+n];
            float gg = (p2[(0*416 + 0*JP + 2*HP+n)*PSTRIDE + ur] + p2[(0*416 + 1*JP + 2*HP+n)*PSTRIDE + ur])
                     + (p2[(1*416 + 0*JP + 2*HP+n)*PSTRIDE + ur] + p2[(1*416 + 1*JP + 2*HP+n)*PSTRIDE + ur])
                     + b2s[2*HP+n];
            float go = (p2[(0*416 + 0*JP + 3*HP+n)*PSTRIDE + ur] + p2[(0*416 + 1*JP + 3*HP+n)*PSTRIDE + ur])
                     + (p2[(1*416 + 0*JP + 3*HP+n)*PSTRIDE + ur] + p2[(1*416 + 1*JP + 3*HP+n)*PSTRIDE + ur])
                     + b2s[3*HP+n];
            c2 = siga(gf)*c2 + siga(gi)*tanha(gg);
            h2s[n*RR + ur] = siga(go)*tanha(c2);
        }
        if (tid >= RR && tid < 2*RR && (t + 1) < TT) xs[tid - RR] = xnext;
        __syncthreads();
    }

    // final output column (t = TT-1)
    if (tid < RR) {
        float s0 = 0.f, s1 = 0.f, s2 = 0.f, s3 = 0.f;
#pragma unroll
        for (int n = 0; n < HP; n += 4) {
            s0 = fmaf(wls[n+0], h2s[(n+0)*RR + tid], s0);
            s1 = fmaf(wls[n+1], h2s[(n+1)*RR + tid], s1);
            s2 = fmaf(wls[n+2], h2s[(n+2)*RR + tid], s2);
            s3 = fmaf(wls[n+3], h2s[(n+3)*RR + tid], s3);
        }
        out[(row0 + tid)*TT + (TT - 1)] = (s0 + s1) + (s2 + s3) + blin;
    }
}

extern "C" void kernel_launch(void* const* d_in, const int* in_sizes, int n_in,
                              void* d_out, int out_size)
{
    const float* input = (const float*)d_in[0];
    const float* W_ih1 = (const float*)d_in[1];
    const float* W_hh1 = (const float*)d_in[2];
    const float* b_ih1 = (const float*)d_in[3];
    const float* b_hh1 = (const float*)d_in[4];
    const float* W_ih2 = (const float*)d_in[5];
    const float* W_hh2 = (const float*)d_in[6];
    const float* b_ih2 = (const float*)d_in[7];
    const float* b_hh2 = (const float*)d_in[8];
    const float* W_lin = (const float*)d_in[9];
    const float* b_lin = (const float*)d_in[10];
    float* out = (float*)d_out;

    const int smem_bytes = (NT*PSTRIDE*2 + HP*RR*2 + RR + HP + JP) * (int)sizeof(float);
    cudaFuncSetAttribute(lstm_kernel, cudaFuncAttributeMaxDynamicSharedMemorySize, smem_bytes);

    prep_kernel<<<64, 256>>>(W_ih1, W_hh1, b_ih1, b_hh1,
                             W_ih2, W_hh2, b_ih2, b_hh2, W_lin, b_lin);
    lstm_kernel<<<BB/RR, NT, smem_bytes>>>(input, out);
}

// round 6
// speedup vs baseline: 2.2048x; 1.0897x over previous
#include <cuda_runtime.h>

// Problem constants (fixed instance: B=2048, T=2048, H=51)
#define H_  51
#define HP  52          // padded hidden
#define JP  208         // 4*HP gate count
#define RR  16          // batch rows per CTA
#define NT  640         // threads per CTA (20 warps)
#define TT  2048
#define BB  2048
#define PS  20          // smem partial stride (conflict-free for 128-bit ops)

// Repacked weights (device globals; prep kernel fills them each launch)
__device__ float g_W1p[HP*JP];   // [k][j] layer-1 W_hh
__device__ float g_W2a[HP*JP];   // [k][j] layer-2 W_ih
__device__ float g_W2b[HP*JP];   // [k][j] layer-2 W_hh
__device__ float g_b1[JP];
__device__ float g_wx[JP];
__device__ float g_b2[JP];
__device__ float g_wlin[HP];
__device__ float g_blin[1];

__global__ void prep_kernel(const float* __restrict__ W_ih1, const float* __restrict__ W_hh1,
                            const float* __restrict__ b_ih1, const float* __restrict__ b_hh1,
                            const float* __restrict__ W_ih2, const float* __restrict__ W_hh2,
                            const float* __restrict__ b_ih2, const float* __restrict__ b_hh2,
                            const float* __restrict__ W_lin, const float* __restrict__ b_lin)
{
    int stride = gridDim.x * blockDim.x;
    int i0 = blockIdx.x * blockDim.x + threadIdx.x;
    for (int idx = i0; idx < HP*JP; idx += stride) {
        int k = idx / JP, j = idx % JP;
        int g = j / HP, n = j % HP;
        bool v = (n < H_) && (k < H_);
        int ro = g*H_ + n;
        g_W1p[idx] = v ? W_hh1[ro*H_ + k] : 0.f;
        g_W2a[idx] = v ? W_ih2[ro*H_ + k] : 0.f;
        g_W2b[idx] = v ? W_hh2[ro*H_ + k] : 0.f;
    }
    for (int j = i0; j < JP; j += stride) {
        int g = j / HP, n = j % HP;
        bool v = (n < H_);
        int ro = g*H_ + n;
        g_b1[j] = v ? (b_ih1[ro] + b_hh1[ro]) : 0.f;
        g_wx[j] = v ? W_ih1[ro] : 0.f;
        g_b2[j] = v ? (b_ih2[ro] + b_hh2[ro]) : 0.f;
    }
    for (int n = i0; n < HP; n += stride) g_wlin[n] = (n < H_) ? W_lin[n] : 0.f;
    if (i0 == 0) g_blin[0] = b_lin[0];
}

// HW tanh (single MUFU op)
__device__ __forceinline__ float tanha(float x) {
    float r; asm("tanh.approx.f32 %0, %1;" : "=f"(r) : "f"(x)); return r;
}
__device__ __forceinline__ float siga(float x) {
    return fmaf(0.5f, tanha(0.5f*x), 0.5f);
}

// ---- packed f32x2 helpers (PTX-only; ptxas won't auto-fuse) ----
__device__ __forceinline__ unsigned long long pk2(float w) {
    unsigned long long r;
    asm("mov.b64 %0, {%1, %1};" : "=l"(r) : "f"(w));
    return r;
}
__device__ __forceinline__ void fma2(unsigned long long& a, unsigned long long w, unsigned long long h) {
    asm("fma.rn.f32x2 %0, %1, %2, %3;" : "=l"(a) : "l"(w), "l"(h), "l"(a));
}

__global__ __launch_bounds__(NT, 1)
void lstm_kernel(const float* __restrict__ input, float* __restrict__ out)
{
    extern __shared__ float sm[];
    float* p1  = sm;                   // 416*PS = 8320 floats
    float* p2  = p1 + 416*PS;          // 832*PS = 16640
    float* h1s = p2 + 832*PS;          // HP*RR = 832   layout [k][r]
    float* h2s = h1s + HP*RR;          // 832
    float* xs  = h2s + HP*RR;          // RR
    float* wls = xs + RR;              // HP
    float* b2s = wls + HP;             // JP

    const int tid  = threadIdx.x;
    const int row0 = blockIdx.x * RR;

    const bool isP2 = (tid < 416);
    const bool isP1 = (tid >= 416) && (tid < 624);

    // P2 worker decomposition: q = (kh*2 + src), j-pair (jp, jp+104), K=26
    const int q   = tid / 104;              // 0..3 (only valid for P2)
    const int jp  = tid - q*104;            // 0..103
    const int src = q & 1;                  // 0 = W_ih2·h1, 1 = W_hh2·h2
    const int kh  = q >> 1;                 // 0..1
    // P1 worker decomposition: k-half kh1, j-pair (jp1, jp1+104), K=26
    const int u   = tid - 416;
    const int kh1 = (u >= 0) ? (u / 104) : 0;   // 0..1
    const int jp1 = (u >= 0) ? (u - kh1*104) : 0;

    // update tasks: task tid for all threads, plus task 640+(tid-448) for tid>=448
    const int un  = tid >> 4, ur  = tid & 15;        // n 0..39
    const bool has2 = (tid >= 448);
    const int tk2 = 640 + (tid - 448);
    const int un2 = tk2 >> 4, ur2 = tk2 & 15;        // n 40..51

    // register-resident weights: one 52-entry array per thread (role-dependent)
    float wreg[52];
    float ba = 0.f, bb = 0.f, wxa = 0.f, wxb = 0.f;
    if (isP2) {
        const float* Ws = src ? g_W2b : g_W2a;
#pragma unroll
        for (int kk = 0; kk < 26; kk++) {
            wreg[kk]      = Ws[(kh*26 + kk)*JP + jp];
            wreg[26 + kk] = Ws[(kh*26 + kk)*JP + jp + 104];
        }
    } else if (isP1) {
#pragma unroll
        for (int kk = 0; kk < 26; kk++) {
            wreg[kk]      = g_W1p[(kh1*26 + kk)*JP + jp1];
            wreg[26 + kk] = g_W1p[(kh1*26 + kk)*JP + jp1 + 104];
        }
        ba = g_b1[jp1];  bb = g_b1[jp1 + 104];
        wxa = g_wx[jp1]; wxb = g_wx[jp1 + 104];
    } else {
#pragma unroll
        for (int kk = 0; kk < 52; kk++) wreg[kk] = 0.f;
    }
    const float blin = g_blin[0];

    // cell state
    float c1 = 0.f, c2 = 0.f, c1x = 0.f, c2x = 0.f;

    for (int i = tid; i < HP*RR; i += NT) { h1s[i] = 0.f; h2s[i] = 0.f; }
    for (int i = tid; i < HP; i += NT) wls[i] = g_wlin[i];
    for (int i = tid; i < JP; i += NT) b2s[i] = g_b2[i];
    if (tid >= RR && tid < 2*RR) xs[tid - RR] = input[(row0 + tid - RR)*TT + 0];
    __syncthreads();

    for (int t = 0; t < TT; t++) {
        // prefetch next x (threads 16..31)
        float xnext = 0.f;
        if (tid >= RR && tid < 2*RR && (t + 1) < TT)
            xnext = __ldg(&input[(row0 + tid - RR)*TT + t + 1]);

        // output for step t-1 (threads 0..15; h2s stable until update2)
        if (tid < RR && t > 0) {
            float s0 = 0.f, s1 = 0.f, s2 = 0.f, s3 = 0.f;
#pragma unroll
            for (int n = 0; n < HP; n += 4) {
                s0 = fmaf(wls[n+0], h2s[(n+0)*RR + tid], s0);
                s1 = fmaf(wls[n+1], h2s[(n+1)*RR + tid], s1);
                s2 = fmaf(wls[n+2], h2s[(n+2)*RR + tid], s2);
                s3 = fmaf(wls[n+3], h2s[(n+3)*RR + tid], s3);
            }
            out[(row0 + tid)*TT + (t - 1)] = (s0 + s1) + (s2 + s3) + blin;
        }

        // ---- phase 1 (P1 workers): gates1, j-pair × 26 k's, f32x2 ----
        if (isP1) {
            unsigned long long acc[16];
            if (kh1 == 0) {
                unsigned long long bpA = pk2(ba), wpA = pk2(wxa);
                unsigned long long bpB = pk2(bb), wpB = pk2(wxb);
                const ulonglong2* xv = reinterpret_cast<const ulonglong2*>(xs);
#pragma unroll
                for (int rv = 0; rv < 4; rv++) {
                    ulonglong2 x2 = xv[rv];
                    acc[2*rv+0] = bpA; fma2(acc[2*rv+0], wpA, x2.x);
                    acc[2*rv+1] = bpA; fma2(acc[2*rv+1], wpA, x2.y);
                    acc[8+2*rv+0] = bpB; fma2(acc[8+2*rv+0], wpB, x2.x);
                    acc[8+2*rv+1] = bpB; fma2(acc[8+2*rv+1], wpB, x2.y);
                }
            } else {
#pragma unroll
                for (int i = 0; i < 16; i++) acc[i] = 0ULL;
            }
            const ulonglong2* hbase =
                reinterpret_cast<const ulonglong2*>(h1s + kh1*26*RR);
#pragma unroll
            for (int kk = 0; kk < 26; kk++) {
                unsigned long long wA = pk2(wreg[kk]);
                unsigned long long wB = pk2(wreg[26 + kk]);
#pragma unroll
                for (int rv = 0; rv < 4; rv++) {
                    ulonglong2 h = hbase[kk*4 + rv];
                    fma2(acc[2*rv+0],   wA, h.x);
                    fma2(acc[2*rv+1],   wA, h.y);
                    fma2(acc[8+2*rv+0], wB, h.x);
                    fma2(acc[8+2*rv+1], wB, h.y);
                }
            }
            ulonglong2* pwA = reinterpret_cast<ulonglong2*>(p1 + (kh1*JP + jp1)*PS);
            ulonglong2* pwB = reinterpret_cast<ulonglong2*>(p1 + (kh1*JP + jp1 + 104)*PS);
#pragma unroll
            for (int rv = 0; rv < 4; rv++) {
                ulonglong2 vA; vA.x = acc[2*rv+0];   vA.y = acc[2*rv+1];   pwA[rv] = vA;
                ulonglong2 vB; vB.x = acc[8+2*rv+0]; vB.y = acc[8+2*rv+1]; pwB[rv] = vB;
            }
        }
        __syncthreads();

        // ---- update 1: partials at p1[kh*208 + j], kh ∈ {0,1} ----
        {
            int n = un;
            float gi = p1[(0*JP + 0*HP+n)*PS + ur] + p1[(1*JP + 0*HP+n)*PS + ur];
            float gf = p1[(0*JP + 1*HP+n)*PS + ur] + p1[(1*JP + 1*HP+n)*PS + ur];
            float gg = p1[(0*JP + 2*HP+n)*PS + ur] + p1[(1*JP + 2*HP+n)*PS + ur];
            float go = p1[(0*JP + 3*HP+n)*PS + ur] + p1[(1*JP + 3*HP+n)*PS + ur];
            c1 = siga(gf)*c1 + siga(gi)*tanha(gg);
            h1s[n*RR + ur] = siga(go)*tanha(c1);
        }
        if (has2) {
            int n = un2;
            float gi = p1[(0*JP + 0*HP+n)*PS + ur2] + p1[(1*JP + 0*HP+n)*PS + ur2];
            float gf = p1[(0*JP + 1*HP+n)*PS + ur2] + p1[(1*JP + 1*HP+n)*PS + ur2];
            float gg = p1[(0*JP + 2*HP+n)*PS + ur2] + p1[(1*JP + 2*HP+n)*PS + ur2];
            float go = p1[(0*JP + 3*HP+n)*PS + ur2] + p1[(1*JP + 3*HP+n)*PS + ur2];
            c1x = siga(gf)*c1x + siga(gi)*tanha(gg);
            h1s[n*RR + ur2] = siga(go)*tanha(c1x);
        }
        __syncthreads();

        // ---- phase 2 (P2 workers): W_ih2·h1new or W_hh2·h2, j-pair × 26 k's ----
        if (isP2) {
            unsigned long long acc[16];
#pragma unroll
            for (int i = 0; i < 16; i++) acc[i] = 0ULL;
            const ulonglong2* hbase =
                reinterpret_cast<const ulonglong2*>((src ? h2s : h1s) + kh*26*RR);
#pragma unroll
            for (int kk = 0; kk < 26; kk++) {
                unsigned long long wA = pk2(wreg[kk]);
                unsigned long long wB = pk2(wreg[26 + kk]);
#pragma unroll
                for (int rv = 0; rv < 4; rv++) {
                    ulonglong2 h = hbase[kk*4 + rv];
                    fma2(acc[2*rv+0],   wA, h.x);
                    fma2(acc[2*rv+1],   wA, h.y);
                    fma2(acc[8+2*rv+0], wB, h.x);
                    fma2(acc[8+2*rv+1], wB, h.y);
                }
            }
            ulonglong2* pwA = reinterpret_cast<ulonglong2*>(p2 + (q*JP + jp)*PS);
            ulonglong2* pwB = reinterpret_cast<ulonglong2*>(p2 + (q*JP + jp + 104)*PS);
#pragma unroll
            for (int rv = 0; rv < 4; rv++) {
                ulonglong2 vA; vA.x = acc[2*rv+0];   vA.y = acc[2*rv+1];   pwA[rv] = vA;
                ulonglong2 vB; vB.x = acc[8+2*rv+0]; vB.y = acc[8+2*rv+1]; pwB[rv] = vB;
            }
        }
        __syncthreads();

        // ---- update 2: partials at p2[q*208 + j], q ∈ 0..3, + bias ----
        {
            int n = un;
            float gi = (p2[(0*JP + 0*HP+n)*PS + ur] + p2[(1*JP + 0*HP+n)*PS + ur])
                     + (p2[(2*JP + 0*HP+n)*PS + ur] + p2[(3*JP + 0*HP+n)*PS + ur]) + b2s[0*HP+n];
            float gf = (p2[(0*JP + 1*HP+n)*PS + ur] + p2[(1*JP + 1*HP+n)*PS + ur])
                     + (p2[(2*JP + 1*HP+n)*PS + ur] + p2[(3*JP + 1*HP+n)*PS + ur]) + b2s[1*HP+n];
            float gg = (p2[(0*JP + 2*HP+n)*PS + ur] + p2[(1*JP + 2*HP+n)*PS + ur])
                     + (p2[(2*JP + 2*HP+n)*PS + ur] + p2[(3*JP + 2*HP+n)*PS + ur]) + b2s[2*HP+n];
            float go = (p2[(0*JP + 3*HP+n)*PS + ur] + p2[(1*JP + 3*HP+n)*PS + ur])
                     + (p2[(2*JP + 3*HP+n)*PS + ur] + p2[(3*JP + 3*HP+n)*PS + ur]) + b2s[3*HP+n];
            c2 = siga(gf)*c2 + siga(gi)*tanha(gg);
            h2s[n*RR + ur] = siga(go)*tanha(c2);
        }
        if (has2) {
            int n = un2;
            float gi = (p2[(0*JP + 0*HP+n)*PS + ur2] + p2[(1*JP + 0*HP+n)*PS + ur2])
                     + (p2[(2*JP + 0*HP+n)*PS + ur2] + p2[(3*JP + 0*HP+n)*PS + ur2]) + b2s[0*HP+n];
            float gf = (p2[(0*JP + 1*HP+n)*PS + ur2] + p2[(1*JP + 1*HP+n)*PS + ur2])
                     + (p2[(2*JP + 1*HP+n)*PS + ur2] + p2[(3*JP + 1*HP+n)*PS + ur2]) + b2s[1*HP+n];
            float gg = (p2[(0*JP + 2*HP+n)*PS + ur2] + p2[(1*JP + 2*HP+n)*PS + ur2])
                     + (p2[(2*JP + 2*HP+n)*PS + ur2] + p2[(3*JP + 2*HP+n)*PS + ur2]) + b2s[2*HP+n];
            float go = (p2[(0*JP + 3*HP+n)*PS + ur2] + p2[(1*JP + 3*HP+n)*PS + ur2])
                     + (p2[(2*JP + 3*HP+n)*PS + ur2] + p2[(3*JP + 3*HP+n)*PS + ur2]) + b2s[3*HP+n];
            c2x = siga(gf)*c2x + siga(gi)*tanha(gg);
            h2s[n*RR + ur2] = siga(go)*tanha(c2x);
        }
        if (tid >= RR && tid < 2*RR && (t + 1) < TT) xs[tid - RR] = xnext;
        __syncthreads();
    }

    // final output column (t = TT-1)
    if (tid < RR) {
        float s0 = 0.f, s1 = 0.f, s2 = 0.f, s3 = 0.f;
#pragma unroll
        for (int n = 0; n < HP; n += 4) {
            s0 = fmaf(wls[n+0], h2s[(n+0)*RR + tid], s0);
            s1 = fmaf(wls[n+1], h2s[(n+1)*RR + tid], s1);
            s2 = fmaf(wls[n+2], h2s[(n+2)*RR + tid], s2);
            s3 = fmaf(wls[n+3], h2s[(n+3)*RR + tid], s3);
        }
        out[(row0 + tid)*TT + (TT - 1)] = (s0 + s1) + (s2 + s3) + blin;
    }
}

extern "C" void kernel_launch(void* const* d_in, const int* in_sizes, int n_in,
                              void* d_out, int out_size)
{
    const float* input = (const float*)d_in[0];
    const float* W_ih1 = (const float*)d_in[1];
    const float* W_hh1 = (const float*)d_in[2];
    const float* b_ih1 = (const float*)d_in[3];
    const float* b_hh1 = (const float*)d_in[4];
    const float* W_ih2 = (const float*)d_in[5];
    const float* W_hh2 = (const float*)d_in[6];
    const float* b_ih2 = (const float*)d_in[7];
    const float* b_hh2 = (const float*)d_in[8];
    const float* W_lin = (const float*)d_in[9];
    const float* b_lin = (const float*)d_in[10];
    float* out = (float*)d_out;

    const int smem_bytes = (416*PS + 832*PS + HP*RR*2 + RR + HP + JP) * (int)sizeof(float);
    cudaFuncSetAttribute(lstm_kernel, cudaFuncAttributeMaxDynamicSharedMemorySize, smem_bytes);

    prep_kernel<<<64, 256>>>(W_ih1, W_hh1, b_ih1, b_hh1,
                             W_ih2, W_hh2, b_ih2, b_hh2, W_lin, b_lin);
    lstm_kernel<<<BB/RR, NT, smem_bytes>>>(input, out);
}